// round 8
// baseline (speedup 1.0000x reference)
#include <cuda_runtime.h>
#include <cuda_bf16.h>

#define NN 20000
#define NE 100000
#define ND 128
#define ED 128
#define EIN 291
#define HH 64
#define EPB 8          // for embed/classify kernels

// mpn_step GEMM config
#define BLK_E 128      // edges per block
#define NTH   256      // threads per block

// Scratch (device globals; no allocation allowed)
__device__ float g_nf0[NN * ND];
__device__ float g_nfA[NN * ND];
__device__ float g_nfB[NN * ND];
__device__ float g_ef0[NE * ED];
__device__ float g_ef [NE * ED];
// transposed weights [col][k]
__device__ float g_mew0T[64 * 768];
__device__ float g_mew1T[128 * 64];
__device__ float g_mnw0T[128 * 384];

// ---------------------------------------------------------------------------
// f32x2 packed helpers (Blackwell FFMA2 path — PTX only)
// ---------------------------------------------------------------------------
__device__ __forceinline__ void fma2(unsigned long long& d,
                                     unsigned long long a, unsigned long long b) {
    asm("fma.rn.f32x2 %0, %1, %2, %0;" : "+l"(d) : "l"(a), "l"(b));
}
__device__ __forceinline__ unsigned long long pk2(float lo, float hi) {
    unsigned long long r;
    asm("mov.b64 %0, {%1, %2};" : "=l"(r) : "f"(lo), "f"(hi));
    return r;
}
__device__ __forceinline__ void upk2(float& lo, float& hi, unsigned long long v) {
    asm("mov.b64 {%0, %1}, %2;" : "=f"(lo), "=f"(hi) : "l"(v));
}

// ---------------------------------------------------------------------------
// One-time weight transpose: wT[c][k] = w[k][c]
// ---------------------------------------------------------------------------
__global__ void transpose_weights(const float* __restrict__ mew0,
                                  const float* __restrict__ mew1,
                                  const float* __restrict__ mnw0)
{
    const int i = blockIdx.x * blockDim.x + threadIdx.x;
    if (i < 768 * 64)  { int k = i >> 6, c = i & 63;  g_mew0T[c * 768 + k] = mew0[i]; }
    if (i < 64 * 128)  { int k = i >> 7, c = i & 127; g_mew1T[c * 64  + k] = mew1[i]; }
    if (i < 384 * 128) { int k = i >> 7, c = i & 127; g_mnw0T[c * 384 + k] = mnw0[i]; }
}

// ---------------------------------------------------------------------------
// Node embedding: nf0 = lin(relu(lin(x, new0)), new1)   [N,128]
// ---------------------------------------------------------------------------
__global__ void node_embed_kernel(const float* __restrict__ x,
                                  const float* __restrict__ w0, const float* __restrict__ b0,
                                  const float* __restrict__ w1, const float* __restrict__ b1)
{
    __shared__ float s_x[EPB][ND];
    __shared__ float s_h[EPB][ND];
    const int t = threadIdx.x;
    const int nb = blockIdx.x * EPB;

    #pragma unroll
    for (int r = 0; r < EPB; r++) s_x[r][t] = x[(nb + r) * ND + t];
    __syncthreads();

    float acc[EPB];
    {
        const float b = b0[t];
        #pragma unroll
        for (int r = 0; r < EPB; r++) acc[r] = b;
        #pragma unroll 4
        for (int k = 0; k < ND; k += 4) {
            float4 w4;
            w4.x = w0[(k + 0) * ND + t];
            w4.y = w0[(k + 1) * ND + t];
            w4.z = w0[(k + 2) * ND + t];
            w4.w = w0[(k + 3) * ND + t];
            #pragma unroll
            for (int r = 0; r < EPB; r++) {
                const float4 v = *(const float4*)&s_x[r][k];
                acc[r] += v.x * w4.x + v.y * w4.y + v.z * w4.z + v.w * w4.w;
            }
        }
        #pragma unroll
        for (int r = 0; r < EPB; r++) s_h[r][t] = fmaxf(acc[r], 0.f);
    }
    __syncthreads();
    {
        const float b = b1[t];
        #pragma unroll
        for (int r = 0; r < EPB; r++) acc[r] = b;
        #pragma unroll 4
        for (int k = 0; k < ND; k += 4) {
            float4 w4;
            w4.x = w1[(k + 0) * ND + t];
            w4.y = w1[(k + 1) * ND + t];
            w4.z = w1[(k + 2) * ND + t];
            w4.w = w1[(k + 3) * ND + t];
            #pragma unroll
            for (int r = 0; r < EPB; r++) {
                const float4 v = *(const float4*)&s_h[r][k];
                acc[r] += v.x * w4.x + v.y * w4.y + v.z * w4.z + v.w * w4.w;
            }
        }
        #pragma unroll
        for (int r = 0; r < EPB; r++) g_nf0[(nb + r) * ND + t] = acc[r];
    }
}

// ---------------------------------------------------------------------------
// Edge embedding: ef0 = lin(relu(lin(edge_attr, eew0)), eew1)   [E,128]
// ---------------------------------------------------------------------------
__global__ void edge_embed_kernel(const float* __restrict__ ea,
                                  const float* __restrict__ w0, const float* __restrict__ b0,
                                  const float* __restrict__ w1, const float* __restrict__ b1)
{
    __shared__ float s_in[EPB][EIN + 1];
    __shared__ float s_part[128][EPB + 1];
    __shared__ float s_h[EPB][HH];
    const int t = threadIdx.x;
    const int eb = blockIdx.x * EPB;

    #pragma unroll
    for (int r = 0; r < EPB; r++) {
        const float* row = ea + (size_t)(eb + r) * EIN;
        for (int k = t; k < EIN; k += 128) s_in[r][k] = row[k];
    }
    __syncthreads();

    const int c = t & 63, half = t >> 6;
    const int ks = half ? 146 : 0;
    const int ke = half ? EIN : 146;
    float acc[EPB];
    #pragma unroll
    for (int r = 0; r < EPB; r++) acc[r] = 0.f;
    for (int k = ks; k < ke; k++) {
        const float w = w0[k * HH + c];
        #pragma unroll
        for (int r = 0; r < EPB; r++) acc[r] += s_in[r][k] * w;
    }
    #pragma unroll
    for (int r = 0; r < EPB; r++) s_part[t][r] = acc[r];
    __syncthreads();

    if (t < HH) {
        const float b = b0[t];
        #pragma unroll
        for (int r = 0; r < EPB; r++)
            s_h[r][t] = fmaxf(s_part[t][r] + s_part[t + 64][r] + b, 0.f);
    }
    __syncthreads();

    {
        const float b = b1[t];
        float a2[EPB];
        #pragma unroll
        for (int r = 0; r < EPB; r++) a2[r] = b;
        #pragma unroll 4
        for (int k = 0; k < HH; k += 4) {
            float4 w4;
            w4.x = w1[(k + 0) * ED + t];
            w4.y = w1[(k + 1) * ED + t];
            w4.z = w1[(k + 2) * ED + t];
            w4.w = w1[(k + 3) * ED + t];
            #pragma unroll
            for (int r = 0; r < EPB; r++) {
                const float4 v = *(const float4*)&s_h[r][k];
                a2[r] += v.x * w4.x + v.y * w4.y + v.z * w4.z + v.w * w4.w;
            }
        }
        #pragma unroll
        for (int r = 0; r < EPB; r++) {
            const int e = eb + r;
            g_ef0[e * ED + t] = a2[r];
            g_ef [e * ED + t] = a2[r];
        }
    }
}

// ---------------------------------------------------------------------------
__global__ void zero_nf_kernel(int sel)
{
    float* p = sel ? g_nfB : g_nfA;
    const int i = blockIdx.x * blockDim.x + threadIdx.x;
    if (i < NN * ND) p[i] = 0.f;
}

// ---------------------------------------------------------------------------
// mpn_step: three register-tiled GEMMs per 128-edge tile.
// f32x2 lanes = (even k, odd k); acc lo-lane seeded with bias; epilogue lo+hi.
// A in smem [edge][k] (swizzled k4), B staged transposed [col][k] from wT.
// ---------------------------------------------------------------------------
#define SWSE(e) (((e) >> 2) & 7)

__device__ __forceinline__ void gather_chunk(float* sA, const float* __restrict__ src,
                                             const int* ridx, int koff, int t)
{
    const int ge = t & 127, gh = t >> 7;
    const int row = ridx[ge];
    const int se = SWSE(ge);
    const float4* p = (const float4*)(src + (size_t)row * 128 + koff + gh * 32);
    float* base = sA + ge * 64;
    #pragma unroll
    for (int q = 0; q < 8; q++) {
        const int k4 = gh * 8 + q;
        *(float4*)(base + ((k4 ^ se) << 2)) = p[q];
    }
}

__device__ __forceinline__ void stage_bt(float* sBT, const float* __restrict__ wT,
                                         int wstride, int koff, int t)
{
    // sBT[c][k] for 64 cols x 64 k, row stride 68 floats
    #pragma unroll
    for (int r = 0; r < 4; r++) {
        const int idx = t + r * NTH;            // 0..1023
        const int c = idx >> 4, k4 = idx & 15;
        *(float4*)(sBT + c * 68 + (k4 << 2)) =
            *(const float4*)(wT + (size_t)c * wstride + koff + (k4 << 2));
    }
}

__device__ __forceinline__ void gemm_chunk(unsigned long long acc[4][8],
                                           const float* sA, const float* sBT,
                                           int e0, int se, int cg)
{
    #pragma unroll 4
    for (int k4 = 0; k4 < 16; k4++) {
        ulonglong2 a[4];
        #pragma unroll
        for (int p = 0; p < 4; p++)
            a[p] = *(const ulonglong2*)(sA + (e0 + p) * 64 + ((k4 ^ se) << 2));
        #pragma unroll
        for (int cc = 0; cc < 8; cc++) {
            const ulonglong2 b = *(const ulonglong2*)(sBT + (cg + 8 * cc) * 68 + (k4 << 2));
            #pragma unroll
            for (int p = 0; p < 4; p++) {
                fma2(acc[p][cc], a[p].x, b.x);
                fma2(acc[p][cc], a[p].y, b.y);
            }
        }
    }
}

__global__ void __launch_bounds__(NTH, 2)
mpn_step_kernel(const int* __restrict__ ei,
                const float* __restrict__ meb0,
                const float* __restrict__ meb1,
                const float* __restrict__ mnb0,
                int phase, int compute_msg)
{
    extern __shared__ float smf[];
    float* sA  = smf;                    // 128 x 64
    float* sBT = smf + 128 * 64;         // 64 x 68
    int*   sRi = (int*)(sBT + 64 * 68);
    int*   sRj = sRi + BLK_E;
    int*   sRe = sRj + BLK_E;

    const float* __restrict__ nf_in =
        (phase == 0) ? g_nf0 : ((phase & 1) ? g_nfA : g_nfB);
    float* __restrict__ nf_out = (phase & 1) ? g_nfB : g_nfA;

    const int t  = threadIdx.x;
    const int eb = blockIdx.x * BLK_E;
    const int cg = t & 7;
    const int eg = t >> 3;
    const int e0 = eg * 4;
    const int se = eg & 7;

    if (t < BLK_E) {
        int e = eb + t; if (e > NE - 1) e = NE - 1;
        sRe[t] = e;
        sRj[t] = ei[e];
        sRi[t] = ei[NE + e];
    }

    // ============ Phase 1: h = relu(A768 @ mew0 + meb0), 64 cols ===========
    unsigned long long acc1[4][8];
    #pragma unroll
    for (int cc = 0; cc < 8; cc++) {
        const unsigned long long bp = pk2(meb0[cg + 8 * cc], 0.f);
        #pragma unroll
        for (int p = 0; p < 4; p++) acc1[p][cc] = bp;
    }

    #pragma unroll 1
    for (int ch = 0; ch < 12; ch++) {
        __syncthreads();
        const float* src; const int* ridx;
        if (ch < 4)      { src = (ch & 2) ? nf_in : g_nf0; ridx = sRi; }
        else if (ch < 8) { src = (ch & 2) ? nf_in : g_nf0; ridx = sRj; }
        else             { src = (ch & 2) ? g_ef  : g_ef0; ridx = sRe; }
        gather_chunk(sA, src, ridx, (ch & 1) * 64, t);
        stage_bt(sBT, g_mew0T, 768, ch * 64, t);
        __syncthreads();
        gemm_chunk(acc1, sA, sBT, e0, se, cg);
    }

    // h -> sA (same swizzled layout, k = h-col)
    __syncthreads();
    #pragma unroll
    for (int p = 0; p < 4; p++)
        #pragma unroll
        for (int cc = 0; cc < 8; cc++) {
            float lo, hi; upk2(lo, hi, acc1[p][cc]);
            const int col = cg + 8 * cc;
            sA[(e0 + p) * 64 + (((col >> 2) ^ se) << 2) + (col & 3)] =
                fmaxf(lo + hi, 0.f);
        }

    // ============ Phase 2: ef = relu(h @ mew1 + meb1), 128 cols (2 passes) =
    #pragma unroll 1
    for (int hp = 0; hp < 2; hp++) {
        __syncthreads();
        stage_bt(sBT, g_mew1T + (size_t)hp * 64 * 64, 64, 0, t);
        __syncthreads();
        unsigned long long acc2[4][8];
        #pragma unroll
        for (int cc = 0; cc < 8; cc++) {
            const unsigned long long bp = pk2(meb1[hp * 64 + cg + 8 * cc], 0.f);
            #pragma unroll
            for (int p = 0; p < 4; p++) acc2[p][cc] = bp;
        }
        gemm_chunk(acc2, sA, sBT, e0, se, cg);
        #pragma unroll
        for (int p = 0; p < 4; p++) {
            const int e = eb + e0 + p;
            if (e < NE) {
                float* dst = g_ef + (size_t)e * 128 + hp * 64;
                #pragma unroll
                for (int cc = 0; cc < 8; cc++) {
                    float lo, hi; upk2(lo, hi, acc2[p][cc]);
                    dst[cg + 8 * cc] = fmaxf(lo + hi, 0.f);
                }
            }
        }
    }

    if (!compute_msg) return;

    // ====== Phase 3: msg = relu([x_i|ef] @ mnw0 + mnb0); scatter-add =======
    #pragma unroll 1
    for (int hp = 0; hp < 2; hp++) {
        unsigned long long acc3[4][8];
        #pragma unroll
        for (int cc = 0; cc < 8; cc++) {
            const unsigned long long bp = pk2(mnb0[hp * 64 + cg + 8 * cc], 0.f);
            #pragma unroll
            for (int p = 0; p < 4; p++) acc3[p][cc] = bp;
        }
        #pragma unroll 1
        for (int ch = 0; ch < 6; ch++) {
            __syncthreads();
            const float* src; const int* ridx;
            if (ch < 2)      { src = g_nf0; ridx = sRi; }
            else if (ch < 4) { src = nf_in; ridx = sRi; }
            else             { src = g_ef;  ridx = sRe; }
            gather_chunk(sA, src, ridx, (ch & 1) * 64, t);
            stage_bt(sBT, g_mnw0T + (size_t)hp * 64 * 384, 384, ch * 64, t);
            __syncthreads();
            gemm_chunk(acc3, sA, sBT, e0, se, cg);
        }
        #pragma unroll
        for (int p = 0; p < 4; p++) {
            const int e = eb + e0 + p;
            if (e < NE) {
                float* dst = nf_out + (size_t)sRi[e0 + p] * 128 + hp * 64;
                #pragma unroll
                for (int cc = 0; cc < 8; cc++) {
                    float lo, hi; upk2(lo, hi, acc3[p][cc]);
                    atomicAdd(dst + cg + 8 * cc, fmaxf(lo + hi, 0.f));
                }
            }
        }
    }
}

// ---------------------------------------------------------------------------
// Classifier: out = lin(relu(lin(relu(lin(ef, cw0)), cw1)), cw2)  [E,1]
// ---------------------------------------------------------------------------
__global__ void classify_kernel(float* __restrict__ out,
                                const float* __restrict__ cw0, const float* __restrict__ cb0,
                                const float* __restrict__ cw1, const float* __restrict__ cb1,
                                const float* __restrict__ cw2, const float* __restrict__ cb2)
{
    __shared__ float s_ef[EPB][ED];
    __shared__ float s_h0[EPB][64];
    __shared__ float s_h1[EPB][32];
    const int t = threadIdx.x;
    const int eb = blockIdx.x * EPB;

    #pragma unroll
    for (int r = 0; r < EPB; r++) s_ef[r][t] = g_ef[(eb + r) * ED + t];
    __syncthreads();

    if (t < 64) {
        const float b = cb0[t];
        float a[EPB];
        #pragma unroll
        for (int r = 0; r < EPB; r++) a[r] = b;
        #pragma unroll 4
        for (int k = 0; k < 128; k += 4) {
            float4 w4;
            w4.x = cw0[(k + 0) * 64 + t];
            w4.y = cw0[(k + 1) * 64 + t];
            w4.z = cw0[(k + 2) * 64 + t];
            w4.w = cw0[(k + 3) * 64 + t];
            #pragma unroll
            for (int r = 0; r < EPB; r++) {
                const float4 v = *(const float4*)&s_ef[r][k];
                a[r] += v.x * w4.x + v.y * w4.y + v.z * w4.z + v.w * w4.w;
            }
        }
        #pragma unroll
        for (int r = 0; r < EPB; r++) s_h0[r][t] = fmaxf(a[r], 0.f);
    }
    __syncthreads();

    if (t < 32) {
        const float b = cb1[t];
        float a[EPB];
        #pragma unroll
        for (int r = 0; r < EPB; r++) a[r] = b;
        #pragma unroll 4
        for (int k = 0; k < 64; k += 4) {
            float4 w4;
            w4.x = cw1[(k + 0) * 32 + t];
            w4.y = cw1[(k + 1) * 32 + t];
            w4.z = cw1[(k + 2) * 32 + t];
            w4.w = cw1[(k + 3) * 32 + t];
            #pragma unroll
            for (int r = 0; r < EPB; r++) {
                const float4 v = *(const float4*)&s_h0[r][k];
                a[r] += v.x * w4.x + v.y * w4.y + v.z * w4.z + v.w * w4.w;
            }
        }
        #pragma unroll
        for (int r = 0; r < EPB; r++) s_h1[r][t] = fmaxf(a[r], 0.f);
    }
    __syncthreads();

    if (t < 32) {
        const float w2 = cw2[t];
        #pragma unroll
        for (int r = 0; r < EPB; r++) {
            float v = s_h1[r][t] * w2;
            #pragma unroll
            for (int off = 16; off > 0; off >>= 1)
                v += __shfl_down_sync(0xFFFFFFFFu, v, off);
            if (t == 0) out[eb + r] = v + cb2[0];
        }
    }
}

// ---------------------------------------------------------------------------
extern "C" void kernel_launch(void* const* d_in, const int* in_sizes, int n_in,
                              void* d_out, int out_size)
{
    const float* x    = (const float*)d_in[0];
    const float* ea   = (const float*)d_in[1];
    const int*   ei   = (const int*)  d_in[2];
    const float* new0 = (const float*)d_in[3];
    const float* neb0 = (const float*)d_in[4];
    const float* new1 = (const float*)d_in[5];
    const float* neb1 = (const float*)d_in[6];
    const float* eew0 = (const float*)d_in[7];
    const float* eeb0 = (const float*)d_in[8];
    const float* eew1 = (const float*)d_in[9];
    const float* eeb1 = (const float*)d_in[10];
    const float* mew0 = (const float*)d_in[11];
    const float* meb0 = (const float*)d_in[12];
    const float* mew1 = (const float*)d_in[13];
    const float* meb1 = (const float*)d_in[14];
    const float* mnw0 = (const float*)d_in[15];
    const float* mnb0 = (const float*)d_in[16];
    const float* cw0  = (const float*)d_in[17];
    const float* cb0  = (const float*)d_in[18];
    const float* cw1  = (const float*)d_in[19];
    const float* cb1  = (const float*)d_in[20];
    const float* cw2  = (const float*)d_in[21];
    const float* cb2  = (const float*)d_in[22];
    float* out = (float*)d_out;

    const int SMEM_BYTES = (128 * 64 + 64 * 68) * 4 + 3 * BLK_E * 4;
    cudaFuncSetAttribute(mpn_step_kernel,
                         cudaFuncAttributeMaxDynamicSharedMemorySize, SMEM_BYTES);

    transpose_weights<<<(768 * 64 + 255) / 256, 256>>>(mew0, mew1, mnw0);
    node_embed_kernel<<<NN / EPB, 128>>>(x, new0, neb0, new1, neb1);
    edge_embed_kernel<<<NE / EPB, 128>>>(ea, eew0, eeb0, eew1, eeb1);

    const int zgrid = (NN * ND + 255) / 256;
    const int mgrid = (NE + BLK_E - 1) / BLK_E;

    // step 0: in nf0, out A
    zero_nf_kernel<<<zgrid, 256>>>(0);
    mpn_step_kernel<<<mgrid, NTH, SMEM_BYTES>>>(ei, meb0, meb1, mnb0, 0, 1);
    // step 1: in A, out B
    zero_nf_kernel<<<zgrid, 256>>>(1);
    mpn_step_kernel<<<mgrid, NTH, SMEM_BYTES>>>(ei, meb0, meb1, mnb0, 1, 1);
    // step 2: in B, out A
    zero_nf_kernel<<<zgrid, 256>>>(0);
    mpn_step_kernel<<<mgrid, NTH, SMEM_BYTES>>>(ei, meb0, meb1, mnb0, 2, 1);
    // step 3: in A; final nf never consumed -> skip message/aggregation
    mpn_step_kernel<<<mgrid, NTH, SMEM_BYTES>>>(ei, meb0, meb1, mnb0, 3, 0);

    classify_kernel<<<NE / EPB, 128>>>(out, cw0, cb0, cw1, cb1, cw2, cb2);
}